// round 16
// baseline (speedup 1.0000x reference)
#include <cuda_runtime.h>
#include <cuda_bf16.h>
#include <cuda_fp16.h>
#include <cstdint>

// Problem constants
#define BB   2
#define SEQ  2048
#define DIMM 768
#define NH   12
#define HD   64

// ---------------------------------------------------------------------------
// Scratch (device globals: cudaMalloc is banned)
// ---------------------------------------------------------------------------
__device__ float         g_V [BB * SEQ * DIMM];           // fp32 V (pre-transpose)
__device__ __nv_bfloat16 g_Xh[BB * SEQ * DIMM];           // X hi/lo (for QKV GEMM)
__device__ __nv_bfloat16 g_Xl[BB * SEQ * DIMM];
__device__ __nv_bfloat16 g_Wh[3 * DIMM * DIMM];           // Wq|Wk|Wv hi/lo
__device__ __nv_bfloat16 g_Wl[3 * DIMM * DIMM];
__device__ __nv_bfloat16 g_Qh[24 * SEQ * HD];             // [bh][q][d] hi
__device__ __nv_bfloat16 g_Ql[24 * SEQ * HD];
__device__ __nv_bfloat16 g_Kh[24 * SEQ * HD];
__device__ __nv_bfloat16 g_Kl[24 * SEQ * HD];
__device__ __half        g_Vt[24 * HD * SEQ];             // [bh][d][k] fp16 (transposed)
__device__ float g_E[100663296];                          // [bh][q][k] (403 MB)
__device__ float g_Dinv[8388608];                         // [b][q][k]  (34 MB)

// ---------------------------------------------------------------------------
// bf16 split helpers
// ---------------------------------------------------------------------------
__device__ __forceinline__ unsigned pkbf(__nv_bfloat16 a, __nv_bfloat16 b) {
    return ((unsigned)__bfloat16_as_ushort(b) << 16) | (unsigned)__bfloat16_as_ushort(a);
}
__device__ __forceinline__ void bsplit4(float4 v, uint2 &hi, uint2 &lo) {
    __nv_bfloat16 h0 = __float2bfloat16(v.x);
    __nv_bfloat16 h1 = __float2bfloat16(v.y);
    __nv_bfloat16 h2 = __float2bfloat16(v.z);
    __nv_bfloat16 h3 = __float2bfloat16(v.w);
    __nv_bfloat16 l0 = __float2bfloat16(v.x - __bfloat162float(h0));
    __nv_bfloat16 l1 = __float2bfloat16(v.y - __bfloat162float(h1));
    __nv_bfloat16 l2 = __float2bfloat16(v.z - __bfloat162float(h2));
    __nv_bfloat16 l3 = __float2bfloat16(v.w - __bfloat162float(h3));
    hi.x = pkbf(h0, h1); hi.y = pkbf(h2, h3);
    lo.x = pkbf(l0, l1); lo.y = pkbf(l2, l3);
}
__device__ __forceinline__ unsigned bsplit2(float a, float b, unsigned &lo) {
    __nv_bfloat16 h0 = __float2bfloat16(a);
    __nv_bfloat16 h1 = __float2bfloat16(b);
    lo = pkbf(__float2bfloat16(a - __bfloat162float(h0)),
              __float2bfloat16(b - __bfloat162float(h1)));
    return pkbf(h0, h1);
}
__device__ __forceinline__ unsigned pkh2(float a, float b) {
    __half2 h = __floats2half2_rn(a, b);
    return *(unsigned*)&h;
}

// ---------------------------------------------------------------------------
// Portable tensor-core plumbing: ldmatrix + mma.sync (sm_80+ ISA — tcgen05 is
// rejected by the harness's compute_103 lowering).
// ---------------------------------------------------------------------------
__device__ __forceinline__ uint32_t smem_u32(const void* p) {
    uint32_t a;
    asm("{ .reg .u64 t; cvta.to.shared.u64 t, %1; cvt.u32.u64 %0, t; }" : "=r"(a) : "l"(p));
    return a;
}
__device__ __forceinline__ void ldsm4(uint32_t* r, uint32_t addr) {
    asm volatile("ldmatrix.sync.aligned.m8n8.x4.shared.b16 {%0,%1,%2,%3}, [%4];"
                 : "=r"(r[0]), "=r"(r[1]), "=r"(r[2]), "=r"(r[3]) : "r"(addr));
}
__device__ __forceinline__ void mma16816(float* c, const uint32_t* a,
                                         uint32_t b0, uint32_t b1) {
    asm volatile(
        "mma.sync.aligned.m16n8k16.row.col.f32.bf16.bf16.f32 "
        "{%0,%1,%2,%3}, {%4,%5,%6,%7}, {%8,%9}, {%0,%1,%2,%3};"
        : "+f"(c[0]), "+f"(c[1]), "+f"(c[2]), "+f"(c[3])
        : "r"(a[0]), "r"(a[1]), "r"(a[2]), "r"(a[3]), "r"(b0), "r"(b1));
}
__device__ __forceinline__ void mma16816h(float* c, const uint32_t* a,
                                          uint32_t b0, uint32_t b1) {
    asm volatile(
        "mma.sync.aligned.m16n8k16.row.col.f32.f16.f16.f32 "
        "{%0,%1,%2,%3}, {%4,%5,%6,%7}, {%8,%9}, {%0,%1,%2,%3};"
        : "+f"(c[0]), "+f"(c[1]), "+f"(c[2]), "+f"(c[3])
        : "r"(a[0]), "r"(a[1]), "r"(a[2]), "r"(a[3]), "r"(b0), "r"(b1));
}
__device__ __forceinline__ void cpa16(uint32_t dst, const void* src) {
    asm volatile("cp.async.cg.shared.global [%0], [%1], 16;"
                 :: "r"(dst), "l"((unsigned long long)__cvta_generic_to_global(src)));
}
#define CPA_COMMIT() asm volatile("cp.async.commit_group;" ::: "memory")
#define CPA_WAIT(n)  asm volatile("cp.async.wait_group %0;" :: "n"(n) : "memory")

// Padded SMEM tile strides: 64-col tiles 144B, 128-col tiles 272B.
#define TPAD_B  144
#define TPAD2_B 272

// ---------------------------------------------------------------------------
// Kernel 0: split fp32 -> bf16 hi/lo (X)
// ---------------------------------------------------------------------------
__global__ void __launch_bounds__(256) k_split(const float* __restrict__ src,
                                               __nv_bfloat16* __restrict__ dh,
                                               __nv_bfloat16* __restrict__ dl,
                                               int n4)
{
    int i = blockIdx.x * 256 + threadIdx.x;
    if (i >= n4) return;
    float4 v = ((const float4*)src)[i];
    uint2 hi, lo; bsplit4(v, hi, lo);
    *(uint2*)(dh + (size_t)i * 4) = hi;
    *(uint2*)(dl + (size_t)i * 4) = lo;
}

// Kernel 0b: split all three W matrices in one launch (blockIdx.y selects)
__global__ void __launch_bounds__(256) k_splitw(const float* __restrict__ w0,
                                                const float* __restrict__ w1,
                                                const float* __restrict__ w2)
{
    const int z = blockIdx.y;
    const float* src = (z == 0) ? w0 : (z == 1) ? w1 : w2;
    int i = blockIdx.x * 256 + threadIdx.x;           // 0..147455 (float4)
    float4 v = ((const float4*)src)[i];
    uint2 hi, lo; bsplit4(v, hi, lo);
    size_t off = (size_t)z * (DIMM * DIMM) + (size_t)i * 4;
    *(uint2*)(g_Wh + off) = hi;
    *(uint2*)(g_Wl + off) = lo;
}

// ---------------------------------------------------------------------------
// Kernel 1: QKV projection via mma.sync 3-split: Y = X @ W^T.
// CTA tile 128m x 64n (was 128x128) — stage 55.3 KB, 2-stage ring = 110.6 KB
// -> occ 2 WITH the cp.async pipeline (same recipe that won in escore).
// 8 warps: 4 m-groups of 32, 2 n-groups of 32. k-loop 12 chunks of 64.
// ---------------------------------------------------------------------------
#define QK_XH 0
#define QK_XL 18432
#define QK_WH 36864
#define QK_WL 46080
#define QK_STAGE 55296
#define QK_SMEM (2 * QK_STAGE)

__global__ void __launch_bounds__(256) k_qkv_mma()
{
    extern __shared__ char smem[];
    const uint32_t sb = smem_u32(smem);
    const int tid = threadIdx.x, wid = tid >> 5, lane = tid & 31;
    const int z  = blockIdx.z;
    const int m0 = blockIdx.y * 128;
    const int n0 = blockIdx.x * 64;

    const uint4* Xh4 = (const uint4*)(g_Xh + (size_t)m0 * DIMM);  // pitch 96 uint4
    const uint4* Xl4 = (const uint4*)(g_Xl + (size_t)m0 * DIMM);
    const uint4* Wh4 = (const uint4*)(g_Wh + ((size_t)z * DIMM + n0) * DIMM);
    const uint4* Wl4 = (const uint4*)(g_Wl + ((size_t)z * DIMM + n0) * DIMM);

    const int wq = (wid & 3) * 32;   // warp m-base (4 groups)
    const int wn = (wid >> 2) * 32;  // warp n-base (2 groups)

    float acc[2][4][4];
    #pragma unroll
    for (int mt = 0; mt < 2; mt++)
        #pragma unroll
        for (int nt = 0; nt < 4; nt++)
            #pragma unroll
            for (int j = 0; j < 4; j++) acc[mt][nt][j] = 0.f;

    const uint32_t a_roff = (lane & 15) * TPAD_B;
    const uint32_t a_coff = (lane >> 4) * 16;
    const uint32_t b_roff = ((lane & 7) + ((lane >> 3) & 1) * 8) * TPAD_B;
    const uint32_t b_coff = (lane >> 4) * 16;

    // prologue: stage 0 (kt = 0): X 1024 uint4 per tensor, W 512 per tensor
    {
        #pragma unroll
        for (int i = 0; i < 4; i++) {
            int idx = i * 256 + tid;
            int row = idx >> 3, s = idx & 7;
            cpa16(sb + QK_XH + row * TPAD_B + s * 16, &Xh4[row * 96 + s]);
            cpa16(sb + QK_XL + row * TPAD_B + s * 16, &Xl4[row * 96 + s]);
        }
        #pragma unroll
        for (int i = 0; i < 2; i++) {
            int idx = i * 256 + tid;
            int row = idx >> 3, s = idx & 7;
            cpa16(sb + QK_WH + row * TPAD_B + s * 16, &Wh4[row * 96 + s]);
            cpa16(sb + QK_WL + row * TPAD_B + s * 16, &Wl4[row * 96 + s]);
        }
        CPA_COMMIT();
    }

    #pragma unroll 1
    for (int kt = 0; kt < 12; kt++) {
        const uint32_t cur = (kt & 1) * QK_STAGE;
        if (kt + 1 < 12) {
            const uint32_t nxt = ((kt + 1) & 1) * QK_STAGE;
            const int kb = (kt + 1) * 8;
            #pragma unroll
            for (int i = 0; i < 4; i++) {
                int idx = i * 256 + tid;
                int row = idx >> 3, s = idx & 7;
                cpa16(sb + nxt + QK_XH + row * TPAD_B + s * 16, &Xh4[row * 96 + kb + s]);
                cpa16(sb + nxt + QK_XL + row * TPAD_B + s * 16, &Xl4[row * 96 + kb + s]);
            }
            #pragma unroll
            for (int i = 0; i < 2; i++) {
                int idx = i * 256 + tid;
                int row = idx >> 3, s = idx & 7;
                cpa16(sb + nxt + QK_WH + row * TPAD_B + s * 16, &Wh4[row * 96 + kb + s]);
                cpa16(sb + nxt + QK_WL + row * TPAD_B + s * 16, &Wl4[row * 96 + kb + s]);
            }
            CPA_COMMIT();
            CPA_WAIT(1);
        } else {
            CPA_WAIT(0);
        }
        __syncthreads();

        #pragma unroll
        for (int ks = 0; ks < 4; ks++) {
            uint32_t ah[2][4], al[2][4], bb[2][4];
            #pragma unroll
            for (int mt = 0; mt < 2; mt++) {
                uint32_t base = cur + (wq + mt * 16) * TPAD_B + ks * 32;
                ldsm4(ah[mt], sb + QK_XH + base + a_roff + a_coff);
                ldsm4(al[mt], sb + QK_XL + base + a_roff + a_coff);
            }
            #pragma unroll
            for (int ng = 0; ng < 2; ng++)
                ldsm4(bb[ng], sb + QK_WH + cur + (wn + ng * 16) * TPAD_B + ks * 32 + b_roff + b_coff);
            // pass hi*hi
            #pragma unroll
            for (int mt = 0; mt < 2; mt++)
                #pragma unroll
                for (int ng = 0; ng < 2; ng++) {
                    mma16816(acc[mt][2 * ng],     ah[mt], bb[ng][0], bb[ng][2]);
                    mma16816(acc[mt][2 * ng + 1], ah[mt], bb[ng][1], bb[ng][3]);
                }
            // pass lo*hi
            #pragma unroll
            for (int mt = 0; mt < 2; mt++)
                #pragma unroll
                for (int ng = 0; ng < 2; ng++) {
                    mma16816(acc[mt][2 * ng],     al[mt], bb[ng][0], bb[ng][2]);
                    mma16816(acc[mt][2 * ng + 1], al[mt], bb[ng][1], bb[ng][3]);
                }
            // reload B = W_lo, pass hi*lo
            #pragma unroll
            for (int ng = 0; ng < 2; ng++)
                ldsm4(bb[ng], sb + QK_WL + cur + (wn + ng * 16) * TPAD_B + ks * 32 + b_roff + b_coff);
            #pragma unroll
            for (int mt = 0; mt < 2; mt++)
                #pragma unroll
                for (int ng = 0; ng < 2; ng++) {
                    mma16816(acc[mt][2 * ng],     ah[mt], bb[ng][0], bb[ng][2]);
                    mma16816(acc[mt][2 * ng + 1], ah[mt], bb[ng][1], bb[ng][3]);
                }
        }
        __syncthreads();
    }

    if (z == 2) {
        #pragma unroll
        for (int mt = 0; mt < 2; mt++) {
            const int r = m0 + wq + mt * 16 + (lane >> 2);
            #pragma unroll
            for (int nt = 0; nt < 4; nt++) {
                const int cc = n0 + wn + nt * 8 + (lane & 3) * 2;
                *(float2*)(g_V + (size_t)r * DIMM + cc) =
                    make_float2(acc[mt][nt][0], acc[mt][nt][1]);
                *(float2*)(g_V + (size_t)(r + 8) * DIMM + cc) =
                    make_float2(acc[mt][nt][2], acc[mt][nt][3]);
            }
        }
    } else {
        __nv_bfloat16* OH = (z == 0) ? g_Qh : g_Kh;
        __nv_bfloat16* OL = (z == 0) ? g_Ql : g_Kl;
        #pragma unroll
        for (int mt = 0; mt < 2; mt++) {
            const int m = m0 + wq + mt * 16 + (lane >> 2);
            const int b = m >> 11, q = m & 2047;
            #pragma unroll
            for (int nt = 0; nt < 4; nt++) {
                const int n = n0 + wn + nt * 8 + (lane & 3) * 2;
                const int h = n >> 6, d = n & 63;
                size_t base = ((size_t)(b * NH + h) * SEQ + q) * HD + d;
                unsigned lo0, lo1;
                unsigned hi0 = bsplit2(acc[mt][nt][0], acc[mt][nt][1], lo0);
                unsigned hi1 = bsplit2(acc[mt][nt][2], acc[mt][nt][3], lo1);
                *(unsigned*)(OH + base) = hi0;
                *(unsigned*)(OL + base) = lo0;
                *(unsigned*)(OH + base + 8 * HD) = hi1;
                *(unsigned*)(OL + base + 8 * HD) = lo1;
            }
        }
    }
}

// ---------------------------------------------------------------------------
// Kernel 1b: V transpose + fp16 convert: g_V[b][k][h*64+d] -> g_Vt[bh][d][k]
// ---------------------------------------------------------------------------
__global__ void __launch_bounds__(256) k_vsplit()
{
    __shared__ float sh[64][65];
    const int tid = threadIdx.x;
    const int k0 = blockIdx.x * 64;
    const int bh = blockIdx.y;
    const int b = bh / NH, h = bh % NH;

    #pragma unroll
    for (int i = 0; i < 4; i++) {
        int idx4 = i * 256 + tid;
        int kk = idx4 >> 4, c4 = idx4 & 15;
        float4 v = *(const float4*)(g_V + ((size_t)(b * SEQ + k0 + kk)) * DIMM + h * HD + c4 * 4);
        sh[kk][c4 * 4 + 0] = v.x; sh[kk][c4 * 4 + 1] = v.y;
        sh[kk][c4 * 4 + 2] = v.z; sh[kk][c4 * 4 + 3] = v.w;
    }
    __syncthreads();
    #pragma unroll
    for (int i = 0; i < 2; i++) {
        int idx = i * 256 + tid;
        int d = idx >> 3, s = idx & 7;
        unsigned w[4];
        #pragma unroll
        for (int j = 0; j < 4; j++)
            w[j] = pkh2(sh[s * 8 + j * 2][d], sh[s * 8 + j * 2 + 1][d]);
        size_t dst = ((size_t)bh * HD + d) * SEQ + k0 + s * 8;
        *(uint4*)(g_Vt + dst) = make_uint4(w[0], w[1], w[2], w[3]);
    }
}

// ---------------------------------------------------------------------------
// Kernel 2: FUSED escore + dsum — CTA tile 128q x 64k, double-buffered
// (stage 55.3 KB, 2 stages = 110.6 KB -> occ 2 WITH pipeline).
// ---------------------------------------------------------------------------
#define ES_QH 0
#define ES_QL 18432
#define ES_KH 36864
#define ES_KL 46080
#define ES_STAGE 55296
#define ES_SMEM (2 * ES_STAGE)

__global__ void __launch_bounds__(256) k_escore_fused()
{
    extern __shared__ char smem[];
    const uint32_t sb = smem_u32(smem);
    const int tid = threadIdx.x, wid = tid >> 5, lane = tid & 31;
    const int b  = blockIdx.z;
    const int q0 = blockIdx.y * 128;
    const int k0 = blockIdx.x * 64;

    const uint4* Qh4 = (const uint4*)(g_Qh + ((size_t)(b * NH) * SEQ + q0) * HD);
    const uint4* Ql4 = (const uint4*)(g_Ql + ((size_t)(b * NH) * SEQ + q0) * HD);
    const uint4* Kh4 = (const uint4*)(g_Kh + ((size_t)(b * NH) * SEQ + k0) * HD);
    const uint4* Kl4 = (const uint4*)(g_Kl + ((size_t)(b * NH) * SEQ + k0) * HD);
    const int HSTEP = SEQ * HD / 8;   // per-head offset in uint4

    const int wq = (wid & 3) * 32;    // 4 q-groups of 32
    const int wk = (wid >> 2) * 32;   // 2 k-groups of 32

    const uint32_t a_roff = (lane & 15) * TPAD_B;
    const uint32_t a_coff = (lane >> 4) * 16;
    const uint32_t b_roff = ((lane & 7) + ((lane >> 3) & 1) * 8) * TPAD_B;
    const uint32_t b_coff = (lane >> 4) * 16;

    float dacc[2][4][4];
    #pragma unroll
    for (int mt = 0; mt < 2; mt++)
        #pragma unroll
        for (int nt = 0; nt < 4; nt++)
            #pragma unroll
            for (int j = 0; j < 4; j++) dacc[mt][nt][j] = 0.f;

    // prologue: head 0 into stage 0
    {
        #pragma unroll
        for (int i = 0; i < 4; i++) {
            int idx = i * 256 + tid;
            int row = idx >> 3, s = idx & 7;
            cpa16(sb + ES_QH + row * TPAD_B + s * 16, &Qh4[row * 8 + s]);
            cpa16(sb + ES_QL + row * TPAD_B + s * 16, &Ql4[row * 8 + s]);
        }
        #pragma unroll
        for (int i = 0; i < 2; i++) {
            int idx = i * 256 + tid;
            int row = idx >> 3, s = idx & 7;
            cpa16(sb + ES_KH + row * TPAD_B + s * 16, &Kh4[row * 8 + s]);
            cpa16(sb + ES_KL + row * TPAD_B + s * 16, &Kl4[row * 8 + s]);
        }
        CPA_COMMIT();
    }

    #pragma unroll 1
    for (int h = 0; h < NH; h++) {
        const uint32_t cur = (h & 1) * ES_STAGE;
        if (h + 1 < NH) {
            const uint32_t nxt = ((h + 1) & 1) * ES_STAGE;
            const uint4* qh = Qh4 + (h + 1) * HSTEP;
            const uint4* ql = Ql4 + (h + 1) * HSTEP;
            const uint4* kh = Kh4 + (h + 1) * HSTEP;
            const uint4* kl = Kl4 + (h + 1) * HSTEP;
            #pragma unroll
            for (int i = 0; i < 4; i++) {
                int idx = i * 256 + tid;
                int row = idx >> 3, s = idx & 7;
                cpa16(sb + nxt + ES_QH + row * TPAD_B + s * 16, &qh[row * 8 + s]);
                cpa16(sb + nxt + ES_QL + row * TPAD_B + s * 16, &ql[row * 8 + s]);
            }
            #pragma unroll
            for (int i = 0; i < 2; i++) {
                int idx = i * 256 + tid;
                int row = idx >> 3, s = idx & 7;
                cpa16(sb + nxt + ES_KH + row * TPAD_B + s * 16, &kh[row * 8 + s]);
                cpa16(sb + nxt + ES_KL + row * TPAD_B + s * 16, &kl[row * 8 + s]);
            }
            CPA_COMMIT();
            CPA_WAIT(1);
        } else {
            CPA_WAIT(0);
        }
        __syncthreads();

        float sacc[2][4][4];
        #pragma unroll
        for (int mt = 0; mt < 2; mt++)
            #pragma unroll
            for (int nt = 0; nt < 4; nt++)
                #pragma unroll
                for (int j = 0; j < 4; j++) sacc[mt][nt][j] = 0.f;

        #pragma unroll
        for (int ks = 0; ks < 4; ks++) {
            uint32_t ah[2][4], al[2][4], bb[2][4];
            #pragma unroll
            for (int mt = 0; mt < 2; mt++) {
                uint32_t base = cur + (wq + mt * 16) * TPAD_B + ks * 32;
                ldsm4(ah[mt], sb + ES_QH + base + a_roff + a_coff);
                ldsm4(al[mt], sb + ES_QL + base + a_roff + a_coff);
            }
            #pragma unroll
            for (int ng = 0; ng < 2; ng++)
                ldsm4(bb[ng], sb + ES_KH + cur + (wk + ng * 16) * TPAD_B + ks * 32 + b_roff + b_coff);
            // pass hi*hi
            #pragma unroll
            for (int mt = 0; mt < 2; mt++)
                #pragma unroll
                for (int ng = 0; ng < 2; ng++) {
                    mma16816(sacc[mt][2 * ng],     ah[mt], bb[ng][0], bb[ng][2]);
                    mma16816(sacc[mt][2 * ng + 1], ah[mt], bb[ng][1], bb[ng][3]);
                }
            // pass lo*hi
            #pragma unroll
            for (int mt = 0; mt < 2; mt++)
                #pragma unroll
                for (int ng = 0; ng < 2; ng++) {
                    mma16816(sacc[mt][2 * ng],     al[mt], bb[ng][0], bb[ng][2]);
                    mma16816(sacc[mt][2 * ng + 1], al[mt], bb[ng][1], bb[ng][3]);
                }
            // reload B = K_lo, pass hi*lo
            #pragma unroll
            for (int ng = 0; ng < 2; ng++)
                ldsm4(bb[ng], sb + ES_KL + cur + (wk + ng * 16) * TPAD_B + ks * 32 + b_roff + b_coff);
            #pragma unroll
            for (int mt = 0; mt < 2; mt++)
                #pragma unroll
                for (int ng = 0; ng < 2; ng++) {
                    mma16816(sacc[mt][2 * ng],     ah[mt], bb[ng][0], bb[ng][2]);
                    mma16816(sacc[mt][2 * ng + 1], ah[mt], bb[ng][1], bb[ng][3]);
                }
        }

        // per-head epilogue: exp, D-accumulate, store E (128q x 64k tile)
        float* Eg = g_E + ((size_t)(b * NH + h) * SEQ + q0) * SEQ + k0;
        #pragma unroll
        for (int mt = 0; mt < 2; mt++) {
            const int r = wq + mt * 16 + (lane >> 2);
            #pragma unroll
            for (int nt = 0; nt < 4; nt++) {
                const int cc = wk + nt * 8 + (lane & 3) * 2;
                float e0 = __expf(sacc[mt][nt][0]);
                float e1 = __expf(sacc[mt][nt][1]);
                float e2 = __expf(sacc[mt][nt][2]);
                float e3 = __expf(sacc[mt][nt][3]);
                dacc[mt][nt][0] += e0; dacc[mt][nt][1] += e1;
                dacc[mt][nt][2] += e2; dacc[mt][nt][3] += e3;
                *(float2*)(Eg + (size_t)r * SEQ + cc)       = make_float2(e0, e1);
                *(float2*)(Eg + (size_t)(r + 8) * SEQ + cc) = make_float2(e2, e3);
            }
        }
        __syncthreads();
    }

    // Dinv = (1/sqrt(768)) / D
    const float RS = 0.03608439182435161f;
    float* Dg = g_Dinv + ((size_t)b * SEQ + q0) * SEQ + k0;
    #pragma unroll
    for (int mt = 0; mt < 2; mt++) {
        const int r = wq + mt * 16 + (lane >> 2);
        #pragma unroll
        for (int nt = 0; nt < 4; nt++) {
            const int cc = wk + nt * 8 + (lane & 3) * 2;
            *(float2*)(Dg + (size_t)r * SEQ + cc) =
                make_float2(RS / dacc[mt][nt][0], RS / dacc[mt][nt][1]);
            *(float2*)(Dg + (size_t)(r + 8) * SEQ + cc) =
                make_float2(RS / dacc[mt][nt][2], RS / dacc[mt][nt][3]);
        }
    }
}

// ---------------------------------------------------------------------------
// Kernel 4: out = (E*Dinv) @ V via single fp16 mma.sync (R13 version:
// BK=128, P and V double-buffered, 104 KB smem, occ 2).
// ---------------------------------------------------------------------------
#define AV_P0 0
#define AV_P1 34816
#define AV_V0 69632
#define AV_V1 87040
#define AV_SMEM 104448

__global__ void __launch_bounds__(256) k_av_mma(float* __restrict__ out)
{
    extern __shared__ char smem[];
    const uint32_t sb = smem_u32(smem);
    const int tid = threadIdx.x, wid = tid >> 5, lane = tid & 31;
    const int h = blockIdx.x, b = blockIdx.z;
    const int bh = b * NH + h;
    const int q0 = blockIdx.y * 128;

    const float* Eb = g_E    + ((size_t)bh * SEQ + q0) * SEQ;
    const float* Db = g_Dinv + ((size_t)b  * SEQ + q0) * SEQ;
    const uint4* Vt4 = (const uint4*)(g_Vt + (size_t)bh * HD * SEQ);  // row pitch 256 uint4

    const int wq = (wid & 3) * 32;
    const int wd = (wid >> 2) * 32;

    float acc[2][4][4];
    #pragma unroll
    for (int mt = 0; mt < 2; mt++)
        #pragma unroll
        for (int nt = 0; nt < 4; nt++)
            #pragma unroll
            for (int j = 0; j < 4; j++) acc[mt][nt][j] = 0.f;

    const uint32_t a_roff = (lane & 15) * TPAD2_B;
    const uint32_t a_coff = (lane >> 4) * 16;
    const uint32_t b_roff = ((lane & 7) + ((lane >> 3) & 1) * 8) * TPAD2_B;
    const uint32_t b_coff = (lane >> 4) * 16;

    const uint32_t pbuf[2] = { AV_P0, AV_P1 };
    const uint32_t vbuf[2] = { AV_V0, AV_V1 };

    // prologue: stage chunk 0 (P synchronously, V via cp.async+wait)
    #pragma unroll
    for (int i = 0; i < 4; i++) {
        int idx = i * 256 + tid;
        int d = idx >> 4, s = idx & 15;
        cpa16(sb + AV_V0 + d * TPAD2_B + s * 16, &Vt4[d * 256 + s]);
    }
    CPA_COMMIT();
    #pragma unroll
    for (int i = 0; i < 16; i++) {
        int idx = i * 256 + tid;
        int r = idx >> 5, c8 = idx & 31;
        float4 e  = *(const float4*)(Eb + (size_t)r * SEQ + c8 * 4);
        float4 dn = *(const float4*)(Db + (size_t)r * SEQ + c8 * 4);
        uint2 pw;
        pw.x = pkh2(e.x * dn.x, e.y * dn.y);
        pw.y = pkh2(e.z * dn.z, e.w * dn.w);
        *(uint2*)(smem + AV_P0 + r * TPAD2_B + c8 * 8) = pw;
    }
    CPA_WAIT(0);
    __syncthreads();

    #pragma unroll 1
    for (int kc = 0; kc < 16; kc++) {
        const uint32_t pc = pbuf[kc & 1], vc = vbuf[kc & 1];
        const int has_next = (kc + 1 < 16);
        if (has_next) {
            const uint32_t vn = vbuf[(kc + 1) & 1];
            #pragma unroll
            for (int i = 0; i < 4; i++) {
                int idx = i * 256 + tid;
                int d = idx >> 4, s = idx & 15;
                cpa16(sb + vn + d * TPAD2_B + s * 16, &Vt4[d * 256 + (kc + 1) * 16 + s]);
            }
            CPA_COMMIT();
        }

        // MMA on current chunk
        #pragma unroll
        for (int ks = 0; ks < 8; ks++) {
            uint32_t aa[2][4], bv[2][4];
            #pragma unroll
            for (int mt = 0; mt < 2; mt++)
                ldsm4(aa[mt], sb + pc + (wq + mt * 16) * TPAD2_B + ks * 32 + a_roff + a_coff);
            #pragma unroll
            for (int ng = 0; ng < 2; ng++)
                ldsm4(bv[ng], sb + vc + (wd + ng * 16) * TPAD2_B + ks * 32 + b_roff + b_coff);
            #pragma unroll
            for (int mt = 0; mt < 2; mt++)
                #pragma unroll
                for (int ng = 0; ng < 2; ng++) {
                    mma16816h(acc[mt][2 * ng],     aa[mt], bv[ng][0], bv[ng][2]);
                    mma16816h(acc[mt][2 * ng + 1], aa[mt], bv[ng][1], bv[ng][3]);
                }
        }

        // stage next P chunk
        if (has_next) {
            const uint32_t pn = pbuf[(kc + 1) & 1];
            #pragma unroll
            for (int i = 0; i < 16; i++) {
                int idx = i * 256 + tid;
                int r = idx >> 5, c8 = idx & 31;
                float4 e  = *(const float4*)(Eb + (size_t)r * SEQ + (kc + 1) * 128 + c8 * 4);
                float4 dn = *(const float4*)(Db + (size_t)r * SEQ + (kc + 1) * 128 + c8 * 4);
                uint2 pw;
                pw.x = pkh2(e.x * dn.x, e.y * dn.y);
                pw.y = pkh2(e.z * dn.z, e.w * dn.w);
                *(uint2*)(smem + pn + r * TPAD2_B + c8 * 8) = pw;
            }
            CPA_WAIT(0);
        }
        __syncthreads();
    }

    float* Og = out + ((size_t)(b * SEQ + q0)) * DIMM + h * HD;
    #pragma unroll
    for (int mt = 0; mt < 2; mt++) {
        const int r = wq + mt * 16 + (lane >> 2);
        #pragma unroll
        for (int nt = 0; nt < 4; nt++) {
            const int cc = wd + nt * 8 + (lane & 3) * 2;
            *(float2*)(Og + (size_t)r * DIMM + cc) =
                make_float2(acc[mt][nt][0], acc[mt][nt][1]);
            *(float2*)(Og + (size_t)(r + 8) * DIMM + cc) =
                make_float2(acc[mt][nt][2], acc[mt][nt][3]);
        }
    }
}

// ---------------------------------------------------------------------------
extern "C" void kernel_launch(void* const* d_in, const int* in_sizes, int n_in,
                              void* d_out, int out_size)
{
    const float* x  = (const float*)d_in[0];
    const float* wq = (const float*)d_in[1];
    const float* wk = (const float*)d_in[2];
    const float* wv = (const float*)d_in[3];
    float* out = (float*)d_out;

    cudaFuncSetAttribute(k_qkv_mma,      cudaFuncAttributeMaxDynamicSharedMemorySize, QK_SMEM);
    cudaFuncSetAttribute(k_escore_fused, cudaFuncAttributeMaxDynamicSharedMemorySize, ES_SMEM);
    cudaFuncSetAttribute(k_av_mma,       cudaFuncAttributeMaxDynamicSharedMemorySize, AV_SMEM);

    __nv_bfloat16 *xh, *xl;
    cudaGetSymbolAddress((void**)&xh, g_Xh);
    cudaGetSymbolAddress((void**)&xl, g_Xl);

    k_split <<<3072, 256>>>(x, xh, xl, 786432);
    k_splitw<<<dim3(576, 3), 256>>>(wq, wk, wv);
    k_qkv_mma     <<<dim3(12, 32, 3), 256, QK_SMEM>>>();
    k_vsplit      <<<dim3(32, 24),    256>>>();
    k_escore_fused<<<dim3(32, 16, 2), 256, ES_SMEM>>>();
    k_av_mma      <<<dim3(12, 16, 2), 256, AV_SMEM>>>(out);
}

// round 17
// speedup vs baseline: 1.0863x; 1.0863x over previous
#include <cuda_runtime.h>
#include <cuda_bf16.h>
#include <cuda_fp16.h>
#include <cstdint>

// Problem constants
#define BB   2
#define SEQ  2048
#define DIMM 768
#define NH   12
#define HD   64

// ---------------------------------------------------------------------------
// Scratch (device globals: cudaMalloc is banned)
// ---------------------------------------------------------------------------
__device__ float         g_V [BB * SEQ * DIMM];           // fp32 V (pre-transpose)
__device__ __nv_bfloat16 g_Xh[BB * SEQ * DIMM];           // X hi/lo (for QKV GEMM)
__device__ __nv_bfloat16 g_Xl[BB * SEQ * DIMM];
__device__ __nv_bfloat16 g_Wh[3 * DIMM * DIMM];           // Wq|Wk|Wv hi/lo
__device__ __nv_bfloat16 g_Wl[3 * DIMM * DIMM];
__device__ __nv_bfloat16 g_Qh[24 * SEQ * HD];             // [bh][q][d] hi
__device__ __nv_bfloat16 g_Ql[24 * SEQ * HD];
__device__ __nv_bfloat16 g_Kh[24 * SEQ * HD];
__device__ __nv_bfloat16 g_Kl[24 * SEQ * HD];
__device__ __half        g_Vt[24 * HD * SEQ];             // [bh][d][k] fp16 (transposed)
__device__ float g_E[100663296];                          // [bh][q][k] (403 MB)
__device__ float g_Dinv[8388608];                         // [b][q][k]  (34 MB)

// ---------------------------------------------------------------------------
// bf16 split helpers
// ---------------------------------------------------------------------------
__device__ __forceinline__ unsigned pkbf(__nv_bfloat16 a, __nv_bfloat16 b) {
    return ((unsigned)__bfloat16_as_ushort(b) << 16) | (unsigned)__bfloat16_as_ushort(a);
}
__device__ __forceinline__ void bsplit4(float4 v, uint2 &hi, uint2 &lo) {
    __nv_bfloat16 h0 = __float2bfloat16(v.x);
    __nv_bfloat16 h1 = __float2bfloat16(v.y);
    __nv_bfloat16 h2 = __float2bfloat16(v.z);
    __nv_bfloat16 h3 = __float2bfloat16(v.w);
    __nv_bfloat16 l0 = __float2bfloat16(v.x - __bfloat162float(h0));
    __nv_bfloat16 l1 = __float2bfloat16(v.y - __bfloat162float(h1));
    __nv_bfloat16 l2 = __float2bfloat16(v.z - __bfloat162float(h2));
    __nv_bfloat16 l3 = __float2bfloat16(v.w - __bfloat162float(h3));
    hi.x = pkbf(h0, h1); hi.y = pkbf(h2, h3);
    lo.x = pkbf(l0, l1); lo.y = pkbf(l2, l3);
}
__device__ __forceinline__ unsigned bsplit2(float a, float b, unsigned &lo) {
    __nv_bfloat16 h0 = __float2bfloat16(a);
    __nv_bfloat16 h1 = __float2bfloat16(b);
    lo = pkbf(__float2bfloat16(a - __bfloat162float(h0)),
              __float2bfloat16(b - __bfloat162float(h1)));
    return pkbf(h0, h1);
}
__device__ __forceinline__ unsigned pkh2(float a, float b) {
    __half2 h = __floats2half2_rn(a, b);
    return *(unsigned*)&h;
}

// ---------------------------------------------------------------------------
// Portable tensor-core plumbing: ldmatrix + mma.sync (sm_80+ ISA — tcgen05 is
// rejected by the harness's compute_103 lowering).
// ---------------------------------------------------------------------------
__device__ __forceinline__ uint32_t smem_u32(const void* p) {
    uint32_t a;
    asm("{ .reg .u64 t; cvta.to.shared.u64 t, %1; cvt.u32.u64 %0, t; }" : "=r"(a) : "l"(p));
    return a;
}
__device__ __forceinline__ void ldsm4(uint32_t* r, uint32_t addr) {
    asm volatile("ldmatrix.sync.aligned.m8n8.x4.shared.b16 {%0,%1,%2,%3}, [%4];"
                 : "=r"(r[0]), "=r"(r[1]), "=r"(r[2]), "=r"(r[3]) : "r"(addr));
}
__device__ __forceinline__ void mma16816(float* c, const uint32_t* a,
                                         uint32_t b0, uint32_t b1) {
    asm volatile(
        "mma.sync.aligned.m16n8k16.row.col.f32.bf16.bf16.f32 "
        "{%0,%1,%2,%3}, {%4,%5,%6,%7}, {%8,%9}, {%0,%1,%2,%3};"
        : "+f"(c[0]), "+f"(c[1]), "+f"(c[2]), "+f"(c[3])
        : "r"(a[0]), "r"(a[1]), "r"(a[2]), "r"(a[3]), "r"(b0), "r"(b1));
}
__device__ __forceinline__ void mma16816h(float* c, const uint32_t* a,
                                          uint32_t b0, uint32_t b1) {
    asm volatile(
        "mma.sync.aligned.m16n8k16.row.col.f32.f16.f16.f32 "
        "{%0,%1,%2,%3}, {%4,%5,%6,%7}, {%8,%9}, {%0,%1,%2,%3};"
        : "+f"(c[0]), "+f"(c[1]), "+f"(c[2]), "+f"(c[3])
        : "r"(a[0]), "r"(a[1]), "r"(a[2]), "r"(a[3]), "r"(b0), "r"(b1));
}
__device__ __forceinline__ void cpa16(uint32_t dst, const void* src) {
    asm volatile("cp.async.cg.shared.global [%0], [%1], 16;"
                 :: "r"(dst), "l"((unsigned long long)__cvta_generic_to_global(src)));
}
#define CPA_COMMIT() asm volatile("cp.async.commit_group;" ::: "memory")
#define CPA_WAIT(n)  asm volatile("cp.async.wait_group %0;" :: "n"(n) : "memory")

// Padded SMEM tile strides: 64-col tiles 144B, 128-col tiles 272B.
#define TPAD_B  144
#define TPAD2_B 272

// ---------------------------------------------------------------------------
// Kernel 0: split fp32 -> bf16 hi/lo (X)
// ---------------------------------------------------------------------------
__global__ void __launch_bounds__(256) k_split(const float* __restrict__ src,
                                               __nv_bfloat16* __restrict__ dh,
                                               __nv_bfloat16* __restrict__ dl,
                                               int n4)
{
    int i = blockIdx.x * 256 + threadIdx.x;
    if (i >= n4) return;
    float4 v = ((const float4*)src)[i];
    uint2 hi, lo; bsplit4(v, hi, lo);
    *(uint2*)(dh + (size_t)i * 4) = hi;
    *(uint2*)(dl + (size_t)i * 4) = lo;
}

// Kernel 0b: split all three W matrices in one launch (blockIdx.y selects)
__global__ void __launch_bounds__(256) k_splitw(const float* __restrict__ w0,
                                                const float* __restrict__ w1,
                                                const float* __restrict__ w2)
{
    const int z = blockIdx.y;
    const float* src = (z == 0) ? w0 : (z == 1) ? w1 : w2;
    int i = blockIdx.x * 256 + threadIdx.x;           // 0..147455 (float4)
    float4 v = ((const float4*)src)[i];
    uint2 hi, lo; bsplit4(v, hi, lo);
    size_t off = (size_t)z * (DIMM * DIMM) + (size_t)i * 4;
    *(uint2*)(g_Wh + off) = hi;
    *(uint2*)(g_Wl + off) = lo;
}

// ---------------------------------------------------------------------------
// Kernel 1: QKV projection via mma.sync 3-split (R15/R13 form: CTA 128x128,
// cp.async double-buffered 2-stage ring, 147 KB smem, occ 1).
// ---------------------------------------------------------------------------
#define QK_XH 0
#define QK_XL 18432
#define QK_WH 36864
#define QK_WL 55296
#define QK_STAGE 73728
#define QK_SMEM (2 * QK_STAGE)

__global__ void __launch_bounds__(256) k_qkv_mma()
{
    extern __shared__ char smem[];
    const uint32_t sb = smem_u32(smem);
    const int tid = threadIdx.x, wid = tid >> 5, lane = tid & 31;
    const int z  = blockIdx.z;
    const int m0 = blockIdx.y * 128;
    const int n0 = blockIdx.x * 128;

    const uint4* Xh4 = (const uint4*)(g_Xh + (size_t)m0 * DIMM);  // pitch 96 uint4
    const uint4* Xl4 = (const uint4*)(g_Xl + (size_t)m0 * DIMM);
    const uint4* Wh4 = (const uint4*)(g_Wh + ((size_t)z * DIMM + n0) * DIMM);
    const uint4* Wl4 = (const uint4*)(g_Wl + ((size_t)z * DIMM + n0) * DIMM);

    const int wq = (wid & 3) * 32;   // warp m-base
    const int wn = (wid >> 2) * 64;  // warp n-base

    float acc[2][8][4];
    #pragma unroll
    for (int mt = 0; mt < 2; mt++)
        #pragma unroll
        for (int nt = 0; nt < 8; nt++)
            #pragma unroll
            for (int j = 0; j < 4; j++) acc[mt][nt][j] = 0.f;

    const uint32_t a_roff = (lane & 15) * TPAD_B;
    const uint32_t a_coff = (lane >> 4) * 16;
    const uint32_t b_roff = ((lane & 7) + ((lane >> 3) & 1) * 8) * TPAD_B;
    const uint32_t b_coff = (lane >> 4) * 16;

    // prologue: stage 0 loads (kt = 0)
    {
        const uint4* srcs[4] = { Xh4, Xl4, Wh4, Wl4 };
        const int offs[4] = { QK_XH, QK_XL, QK_WH, QK_WL };
        #pragma unroll
        for (int t = 0; t < 4; t++)
            #pragma unroll
            for (int i = 0; i < 4; i++) {
                int idx = i * 256 + tid;
                int row = idx >> 3, s = idx & 7;
                cpa16(sb + offs[t] + row * TPAD_B + s * 16, &srcs[t][row * 96 + s]);
            }
        CPA_COMMIT();
    }

    #pragma unroll 1
    for (int kt = 0; kt < 12; kt++) {
        const uint32_t cur = (kt & 1) * QK_STAGE;
        if (kt + 1 < 12) {
            const uint32_t nxt = ((kt + 1) & 1) * QK_STAGE;
            const uint4* srcs[4] = { Xh4, Xl4, Wh4, Wl4 };
            const int offs[4] = { QK_XH, QK_XL, QK_WH, QK_WL };
            #pragma unroll
            for (int t = 0; t < 4; t++)
                #pragma unroll
                for (int i = 0; i < 4; i++) {
                    int idx = i * 256 + tid;
                    int row = idx >> 3, s = idx & 7;
                    cpa16(sb + nxt + offs[t] + row * TPAD_B + s * 16,
                          &srcs[t][row * 96 + (kt + 1) * 8 + s]);
                }
            CPA_COMMIT();
            CPA_WAIT(1);
        } else {
            CPA_WAIT(0);
        }
        __syncthreads();

        #pragma unroll
        for (int ks = 0; ks < 4; ks++) {
            uint32_t ah[2][4], al[2][4], bb[4][4];
            #pragma unroll
            for (int mt = 0; mt < 2; mt++) {
                uint32_t base = cur + (wq + mt * 16) * TPAD_B + ks * 32;
                ldsm4(ah[mt], sb + QK_XH + base + a_roff + a_coff);
                ldsm4(al[mt], sb + QK_XL + base + a_roff + a_coff);
            }
            #pragma unroll
            for (int ng = 0; ng < 4; ng++)
                ldsm4(bb[ng], sb + QK_WH + cur + (wn + ng * 16) * TPAD_B + ks * 32 + b_roff + b_coff);
            #pragma unroll
            for (int mt = 0; mt < 2; mt++)
                #pragma unroll
                for (int ng = 0; ng < 4; ng++) {
                    mma16816(acc[mt][2 * ng],     ah[mt], bb[ng][0], bb[ng][2]);
                    mma16816(acc[mt][2 * ng + 1], ah[mt], bb[ng][1], bb[ng][3]);
                }
            #pragma unroll
            for (int mt = 0; mt < 2; mt++)
                #pragma unroll
                for (int ng = 0; ng < 4; ng++) {
                    mma16816(acc[mt][2 * ng],     al[mt], bb[ng][0], bb[ng][2]);
                    mma16816(acc[mt][2 * ng + 1], al[mt], bb[ng][1], bb[ng][3]);
                }
            #pragma unroll
            for (int ng = 0; ng < 4; ng++)
                ldsm4(bb[ng], sb + QK_WL + cur + (wn + ng * 16) * TPAD_B + ks * 32 + b_roff + b_coff);
            #pragma unroll
            for (int mt = 0; mt < 2; mt++)
                #pragma unroll
                for (int ng = 0; ng < 4; ng++) {
                    mma16816(acc[mt][2 * ng],     ah[mt], bb[ng][0], bb[ng][2]);
                    mma16816(acc[mt][2 * ng + 1], ah[mt], bb[ng][1], bb[ng][3]);
                }
        }
        __syncthreads();
    }

    if (z == 2) {
        #pragma unroll
        for (int mt = 0; mt < 2; mt++) {
            const int r = m0 + wq + mt * 16 + (lane >> 2);
            #pragma unroll
            for (int nt = 0; nt < 8; nt++) {
                const int cc = n0 + wn + nt * 8 + (lane & 3) * 2;
                *(float2*)(g_V + (size_t)r * DIMM + cc) =
                    make_float2(acc[mt][nt][0], acc[mt][nt][1]);
                *(float2*)(g_V + (size_t)(r + 8) * DIMM + cc) =
                    make_float2(acc[mt][nt][2], acc[mt][nt][3]);
            }
        }
    } else {
        __nv_bfloat16* OH = (z == 0) ? g_Qh : g_Kh;
        __nv_bfloat16* OL = (z == 0) ? g_Ql : g_Kl;
        #pragma unroll
        for (int mt = 0; mt < 2; mt++) {
            const int m = m0 + wq + mt * 16 + (lane >> 2);
            const int b = m >> 11, q = m & 2047;
            #pragma unroll
            for (int nt = 0; nt < 8; nt++) {
                const int n = n0 + wn + nt * 8 + (lane & 3) * 2;
                const int h = n >> 6, d = n & 63;
                size_t base = ((size_t)(b * NH + h) * SEQ + q) * HD + d;
                unsigned lo0, lo1;
                unsigned hi0 = bsplit2(acc[mt][nt][0], acc[mt][nt][1], lo0);
                unsigned hi1 = bsplit2(acc[mt][nt][2], acc[mt][nt][3], lo1);
                *(unsigned*)(OH + base) = hi0;
                *(unsigned*)(OL + base) = lo0;
                *(unsigned*)(OH + base + 8 * HD) = hi1;
                *(unsigned*)(OL + base + 8 * HD) = lo1;
            }
        }
    }
}

// ---------------------------------------------------------------------------
// Kernel 1b: V transpose + fp16 convert: g_V[b][k][h*64+d] -> g_Vt[bh][d][k]
// ---------------------------------------------------------------------------
__global__ void __launch_bounds__(256) k_vsplit()
{
    __shared__ float sh[64][65];
    const int tid = threadIdx.x;
    const int k0 = blockIdx.x * 64;
    const int bh = blockIdx.y;
    const int b = bh / NH, h = bh % NH;

    #pragma unroll
    for (int i = 0; i < 4; i++) {
        int idx4 = i * 256 + tid;
        int kk = idx4 >> 4, c4 = idx4 & 15;
        float4 v = *(const float4*)(g_V + ((size_t)(b * SEQ + k0 + kk)) * DIMM + h * HD + c4 * 4);
        sh[kk][c4 * 4 + 0] = v.x; sh[kk][c4 * 4 + 1] = v.y;
        sh[kk][c4 * 4 + 2] = v.z; sh[kk][c4 * 4 + 3] = v.w;
    }
    __syncthreads();
    #pragma unroll
    for (int i = 0; i < 2; i++) {
        int idx = i * 256 + tid;
        int d = idx >> 3, s = idx & 7;
        unsigned w[4];
        #pragma unroll
        for (int j = 0; j < 4; j++)
            w[j] = pkh2(sh[s * 8 + j * 2][d], sh[s * 8 + j * 2 + 1][d]);
        size_t dst = ((size_t)bh * HD + d) * SEQ + k0 + s * 8;
        *(uint4*)(g_Vt + dst) = make_uint4(w[0], w[1], w[2], w[3]);
    }
}

// ---------------------------------------------------------------------------
// Kernel 2: FUSED escore + dsum — CTA tile 128q x 64k, double-buffered
// (stage 55.3 KB, 2 stages = 110.6 KB -> occ 2 WITH pipeline). Unchanged.
// ---------------------------------------------------------------------------
#define ES_QH 0
#define ES_QL 18432
#define ES_KH 36864
#define ES_KL 46080
#define ES_STAGE 55296
#define ES_SMEM (2 * ES_STAGE)

__global__ void __launch_bounds__(256) k_escore_fused()
{
    extern __shared__ char smem[];
    const uint32_t sb = smem_u32(smem);
    const int tid = threadIdx.x, wid = tid >> 5, lane = tid & 31;
    const int b  = blockIdx.z;
    const int q0 = blockIdx.y * 128;
    const int k0 = blockIdx.x * 64;

    const uint4* Qh4 = (const uint4*)(g_Qh + ((size_t)(b * NH) * SEQ + q0) * HD);
    const uint4* Ql4 = (const uint4*)(g_Ql + ((size_t)(b * NH) * SEQ + q0) * HD);
    const uint4* Kh4 = (const uint4*)(g_Kh + ((size_t)(b * NH) * SEQ + k0) * HD);
    const uint4* Kl4 = (const uint4*)(g_Kl + ((size_t)(b * NH) * SEQ + k0) * HD);
    const int HSTEP = SEQ * HD / 8;   // per-head offset in uint4

    const int wq = (wid & 3) * 32;    // 4 q-groups of 32
    const int wk = (wid >> 2) * 32;   // 2 k-groups of 32

    const uint32_t a_roff = (lane & 15) * TPAD_B;
    const uint32_t a_coff = (lane >> 4) * 16;
    const uint32_t b_roff = ((lane & 7) + ((lane >> 3) & 1) * 8) * TPAD_B;
    const uint32_t b_coff = (lane >> 4) * 16;

    float dacc[2][4][4];
    #pragma unroll
    for (int mt = 0; mt < 2; mt++)
        #pragma unroll
        for (int nt = 0; nt < 4; nt++)
            #pragma unroll
            for (int j = 0; j < 4; j++) dacc[mt][nt][j] = 0.f;

    // prologue: head 0 into stage 0
    {
        #pragma unroll
        for (int i = 0; i < 4; i++) {
            int idx = i * 256 + tid;
            int row = idx >> 3, s = idx & 7;
            cpa16(sb + ES_QH + row * TPAD_B + s * 16, &Qh4[row * 8 + s]);
            cpa16(sb + ES_QL + row * TPAD_B + s * 16, &Ql4[row * 8 + s]);
        }
        #pragma unroll
        for (int i = 0; i < 2; i++) {
            int idx = i * 256 + tid;
            int row = idx >> 3, s = idx & 7;
            cpa16(sb + ES_KH + row * TPAD_B + s * 16, &Kh4[row * 8 + s]);
            cpa16(sb + ES_KL + row * TPAD_B + s * 16, &Kl4[row * 8 + s]);
        }
        CPA_COMMIT();
    }

    #pragma unroll 1
    for (int h = 0; h < NH; h++) {
        const uint32_t cur = (h & 1) * ES_STAGE;
        if (h + 1 < NH) {
            const uint32_t nxt = ((h + 1) & 1) * ES_STAGE;
            const uint4* qh = Qh4 + (h + 1) * HSTEP;
            const uint4* ql = Ql4 + (h + 1) * HSTEP;
            const uint4* kh = Kh4 + (h + 1) * HSTEP;
            const uint4* kl = Kl4 + (h + 1) * HSTEP;
            #pragma unroll
            for (int i = 0; i < 4; i++) {
                int idx = i * 256 + tid;
                int row = idx >> 3, s = idx & 7;
                cpa16(sb + nxt + ES_QH + row * TPAD_B + s * 16, &qh[row * 8 + s]);
                cpa16(sb + nxt + ES_QL + row * TPAD_B + s * 16, &ql[row * 8 + s]);
            }
            #pragma unroll
            for (int i = 0; i < 2; i++) {
                int idx = i * 256 + tid;
                int row = idx >> 3, s = idx & 7;
                cpa16(sb + nxt + ES_KH + row * TPAD_B + s * 16, &kh[row * 8 + s]);
                cpa16(sb + nxt + ES_KL + row * TPAD_B + s * 16, &kl[row * 8 + s]);
            }
            CPA_COMMIT();
            CPA_WAIT(1);
        } else {
            CPA_WAIT(0);
        }
        __syncthreads();

        float sacc[2][4][4];
        #pragma unroll
        for (int mt = 0; mt < 2; mt++)
            #pragma unroll
            for (int nt = 0; nt < 4; nt++)
                #pragma unroll
                for (int j = 0; j < 4; j++) sacc[mt][nt][j] = 0.f;

        #pragma unroll
        for (int ks = 0; ks < 4; ks++) {
            uint32_t ah[2][4], al[2][4], bb[2][4];
            #pragma unroll
            for (int mt = 0; mt < 2; mt++) {
                uint32_t base = cur + (wq + mt * 16) * TPAD_B + ks * 32;
                ldsm4(ah[mt], sb + ES_QH + base + a_roff + a_coff);
                ldsm4(al[mt], sb + ES_QL + base + a_roff + a_coff);
            }
            #pragma unroll
            for (int ng = 0; ng < 2; ng++)
                ldsm4(bb[ng], sb + ES_KH + cur + (wk + ng * 16) * TPAD_B + ks * 32 + b_roff + b_coff);
            // pass hi*hi
            #pragma unroll
            for (int mt = 0; mt < 2; mt++)
                #pragma unroll
                for (int ng = 0; ng < 2; ng++) {
                    mma16816(sacc[mt][2 * ng],     ah[mt], bb[ng][0], bb[ng][2]);
                    mma16816(sacc[mt][2 * ng + 1], ah[mt], bb[ng][1], bb[ng][3]);
                }
            // pass lo*hi
            #pragma unroll
            for (int mt = 0; mt < 2; mt++)
                #pragma unroll
                for (int ng = 0; ng < 2; ng++) {
                    mma16816(sacc[mt][2 * ng],     al[mt], bb[ng][0], bb[ng][2]);
                    mma16816(sacc[mt][2 * ng + 1], al[mt], bb[ng][1], bb[ng][3]);
                }
            // reload B = K_lo, pass hi*lo
            #pragma unroll
            for (int ng = 0; ng < 2; ng++)
                ldsm4(bb[ng], sb + ES_KL + cur + (wk + ng * 16) * TPAD_B + ks * 32 + b_roff + b_coff);
            #pragma unroll
            for (int mt = 0; mt < 2; mt++)
                #pragma unroll
                for (int ng = 0; ng < 2; ng++) {
                    mma16816(sacc[mt][2 * ng],     ah[mt], bb[ng][0], bb[ng][2]);
                    mma16816(sacc[mt][2 * ng + 1], ah[mt], bb[ng][1], bb[ng][3]);
                }
        }

        // per-head epilogue: exp, D-accumulate, store E (128q x 64k tile)
        float* Eg = g_E + ((size_t)(b * NH + h) * SEQ + q0) * SEQ + k0;
        #pragma unroll
        for (int mt = 0; mt < 2; mt++) {
            const int r = wq + mt * 16 + (lane >> 2);
            #pragma unroll
            for (int nt = 0; nt < 4; nt++) {
                const int cc = wk + nt * 8 + (lane & 3) * 2;
                float e0 = __expf(sacc[mt][nt][0]);
                float e1 = __expf(sacc[mt][nt][1]);
                float e2 = __expf(sacc[mt][nt][2]);
                float e3 = __expf(sacc[mt][nt][3]);
                dacc[mt][nt][0] += e0; dacc[mt][nt][1] += e1;
                dacc[mt][nt][2] += e2; dacc[mt][nt][3] += e3;
                *(float2*)(Eg + (size_t)r * SEQ + cc)       = make_float2(e0, e1);
                *(float2*)(Eg + (size_t)(r + 8) * SEQ + cc) = make_float2(e2, e3);
            }
        }
        __syncthreads();
    }

    // Dinv = (1/sqrt(768)) / D
    const float RS = 0.03608439182435161f;
    float* Dg = g_Dinv + ((size_t)b * SEQ + q0) * SEQ + k0;
    #pragma unroll
    for (int mt = 0; mt < 2; mt++) {
        const int r = wq + mt * 16 + (lane >> 2);
        #pragma unroll
        for (int nt = 0; nt < 4; nt++) {
            const int cc = wk + nt * 8 + (lane & 3) * 2;
            *(float2*)(Dg + (size_t)r * SEQ + cc) =
                make_float2(RS / dacc[mt][nt][0], RS / dacc[mt][nt][1]);
            *(float2*)(Dg + (size_t)(r + 8) * SEQ + cc) =
                make_float2(RS / dacc[mt][nt][2], RS / dacc[mt][nt][3]);
        }
    }
}

// ---------------------------------------------------------------------------
// Kernel 4: out = (E*Dinv) @ V via single fp16 mma.sync.
// CTA tile 64q x 64d (was 128q): stage = P(17.4K) + V(17.4K) = 34.8 KB,
// 2-stage ring = 69.6 KB -> occ 3; grid 768 CTAs of half duration ->
// wave-quantization tail shrinks (384T/296 -> 384T/444 slot model).
// 8 warps: 2 q-groups of 32, 4 d-groups of 16. BK=128 (16 chunks).
// ---------------------------------------------------------------------------
#define AV_P0 0
#define AV_P1 17408
#define AV_V0 34816
#define AV_V1 52224
#define AV_SMEM 69632

__global__ void __launch_bounds__(256) k_av_mma(float* __restrict__ out)
{
    extern __shared__ char smem[];
    const uint32_t sb = smem_u32(smem);
    const int tid = threadIdx.x, wid = tid >> 5, lane = tid & 31;
    const int h = blockIdx.x, b = blockIdx.z;
    const int bh = b * NH + h;
    const int q0 = blockIdx.y * 64;

    const float* Eb = g_E    + ((size_t)bh * SEQ + q0) * SEQ;
    const float* Db = g_Dinv + ((size_t)b  * SEQ + q0) * SEQ;
    const uint4* Vt4 = (const uint4*)(g_Vt + (size_t)bh * HD * SEQ);  // row pitch 256 uint4

    const int wq = (wid & 1) * 32;    // 2 q-groups of 32
    const int wd = (wid >> 1) * 16;   // 4 d-groups of 16

    float acc[2][2][4];
    #pragma unroll
    for (int mt = 0; mt < 2; mt++)
        #pragma unroll
        for (int nt = 0; nt < 2; nt++)
            #pragma unroll
            for (int j = 0; j < 4; j++) acc[mt][nt][j] = 0.f;

    const uint32_t a_roff = (lane & 15) * TPAD2_B;
    const uint32_t a_coff = (lane >> 4) * 16;
    const uint32_t b_roff = ((lane & 7) + ((lane >> 3) & 1) * 8) * TPAD2_B;
    const uint32_t b_coff = (lane >> 4) * 16;

    const uint32_t pbuf[2] = { AV_P0, AV_P1 };
    const uint32_t vbuf[2] = { AV_V0, AV_V1 };

    // prologue: stage chunk 0 (P synchronously, V via cp.async+wait)
    #pragma unroll
    for (int i = 0; i < 4; i++) {
        int idx = i * 256 + tid;
        int d = idx >> 4, s = idx & 15;
        cpa16(sb + AV_V0 + d * TPAD2_B + s * 16, &Vt4[d * 256 + s]);
    }
    CPA_COMMIT();
    #pragma unroll
    for (int i = 0; i < 8; i++) {
        int idx = i * 256 + tid;
        int r = idx >> 5, c8 = idx & 31;
        float4 e  = *(const float4*)(Eb + (size_t)r * SEQ + c8 * 4);
        float4 dn = *(const float4*)(Db + (size_t)r * SEQ + c8 * 4);
        uint2 pw;
        pw.x = pkh2(e.x * dn.x, e.y * dn.y);
        pw.y = pkh2(e.z * dn.z, e.w * dn.w);
        *(uint2*)(smem + AV_P0 + r * TPAD2_B + c8 * 8) = pw;
    }
    CPA_WAIT(0);
    __syncthreads();

    #pragma unroll 1
    for (int kc = 0; kc < 16; kc++) {
        const uint32_t pc = pbuf[kc & 1], vc = vbuf[kc & 1];
        const int has_next = (kc + 1 < 16);
        if (has_next) {
            const uint32_t vn = vbuf[(kc + 1) & 1];
            #pragma unroll
            for (int i = 0; i < 4; i++) {
                int idx = i * 256 + tid;
                int d = idx >> 4, s = idx & 15;
                cpa16(sb + vn + d * TPAD2_B + s * 16, &Vt4[d * 256 + (kc + 1) * 16 + s]);
            }
            CPA_COMMIT();
        }

        // MMA on current chunk
        #pragma unroll
        for (int ks = 0; ks < 8; ks++) {
            uint32_t aa[2][4], bv[4];
            #pragma unroll
            for (int mt = 0; mt < 2; mt++)
                ldsm4(aa[mt], sb + pc + (wq + mt * 16) * TPAD2_B + ks * 32 + a_roff + a_coff);
            ldsm4(bv, sb + vc + wd * TPAD2_B + ks * 32 + b_roff + b_coff);
            #pragma unroll
            for (int mt = 0; mt < 2; mt++) {
                mma16816h(acc[mt][0], aa[mt], bv[0], bv[2]);
                mma16816h(acc[mt][1], aa[mt], bv[1], bv[3]);
            }
        }

        // stage next P chunk
        if (has_next) {
            const uint32_t pn = pbuf[(kc + 1) & 1];
            #pragma unroll
            for (int i = 0; i < 8; i++) {
                int idx = i * 256 + tid;
                int r = idx >> 5, c8 = idx & 31;
                float4 e  = *(const float4*)(Eb + (size_t)r * SEQ + (kc + 1) * 128 + c8 * 4);
                float4 dn = *(const float4*)(Db + (size_t)r * SEQ + (kc + 1) * 128 + c8 * 4);
                uint2 pw;
                pw.x = pkh2(e.x * dn.x, e.y * dn.y);
                pw.y = pkh2(e.z * dn.z, e.w * dn.w);
                *(uint2*)(smem + pn + r * TPAD2_B + c8 * 8) = pw;
            }
            CPA_WAIT(0);
        }
        __syncthreads();
    }

    float* Og = out + ((size_t)(b * SEQ + q0)) * DIMM + h * HD;
    #pragma unroll
    for (int mt = 0; mt < 2; mt++) {
        const int r = wq + mt * 16 + (lane >> 2);
        #pragma unroll
        for (int nt = 0; nt < 2; nt++) {
            const int cc = wd + nt * 8 + (lane & 3) * 2;
            *(float2*)(Og + (size_t)r * DIMM + cc) =
                make_float2(acc[mt][nt][0], acc[mt][nt][1]);
            *(float2*)(Og + (size_t)(r + 8) * DIMM + cc) =
                make_float2(acc[mt][nt][2], acc[mt][nt][3]);
        }
    }
}

// ---------------------------------------------------------------------------
extern "C" void kernel_launch(void* const* d_in, const int* in_sizes, int n_in,
                              void* d_out, int out_size)
{
    const float* x  = (const float*)d_in[0];
    const float* wq = (const float*)d_in[1];
    const float* wk = (const float*)d_in[2];
    const float* wv = (const float*)d_in[3];
    float* out = (float*)d_out;

    cudaFuncSetAttribute(k_qkv_mma,      cudaFuncAttributeMaxDynamicSharedMemorySize, QK_SMEM);
    cudaFuncSetAttribute(k_escore_fused, cudaFuncAttributeMaxDynamicSharedMemorySize, ES_SMEM);
    cudaFuncSetAttribute(k_av_mma,       cudaFuncAttributeMaxDynamicSharedMemorySize, AV_SMEM);

    __nv_bfloat16 *xh, *xl;
    cudaGetSymbolAddress((void**)&xh, g_Xh);
    cudaGetSymbolAddress((void**)&xl, g_Xl);

    k_split <<<3072, 256>>>(x, xh, xl, 786432);
    k_splitw<<<dim3(576, 3), 256>>>(wq, wk, wv);
    k_qkv_mma     <<<dim3(6, 32, 3),  256, QK_SMEM>>>();
    k_vsplit      <<<dim3(32, 24),    256>>>();
    k_escore_fused<<<dim3(32, 16, 2), 256, ES_SMEM>>>();
    k_av_mma      <<<dim3(12, 32, 2), 256, AV_SMEM>>>(out);
}